// round 7
// baseline (speedup 1.0000x reference)
#include <cuda_runtime.h>
#include <cuda_bf16.h>
#include <cstdint>

// AtomicNeuralNetwork: N=4096, A=256, D_IN=39, H=50, S=8
#define D_IN 39
#define H_   50
#define A_   256
#define S_   8
#define TPB  256

// ---- smem layout. Strides 112/144 ≡ 16 (mod 128) -> ldmatrix conflict-free.
#define STR1 112
#define STR2 144
#define A1H  0              // 128*112 = 14336
#define A1L  14336
#define B1H  28672          // 64*112 = 7168
#define B1L  35840
#define B2H  43008          // 64*144 = 9216
#define B2L  52224
#define SB1  61440          // 64 floats
#define SB2  61696
#define SW3  61952
#define SB3  62208
#define SMEM_BYTES 62464

// packed per-species weights: [B1H | B1L | B2H | B2L] in u16 units
#define W_B1H 0
#define W_B1L 3584
#define W_B2H 7168
#define W_B2L 11776
#define W_TOT 16384

__device__ __align__(16) uint16_t g_W[S_][W_TOT];

// ---------------- helpers ----------------
__device__ __forceinline__ uint32_t smem_u32(const void* p) {
    uint32_t a;
    asm("{ .reg .u64 t; cvta.to.shared.u64 t, %1; cvt.u32.u64 %0, t; }" : "=r"(a) : "l"(p));
    return a;
}
__device__ __forceinline__ void ldsm4(uint32_t* r, uint32_t addr) {
    asm volatile("ldmatrix.sync.aligned.m8n8.x4.shared.b16 {%0,%1,%2,%3}, [%4];"
        : "=r"(r[0]), "=r"(r[1]), "=r"(r[2]), "=r"(r[3]) : "r"(addr));
}
__device__ __forceinline__ void mma16816(float* c, const uint32_t* a, const uint32_t* b) {
    asm volatile("mma.sync.aligned.m16n8k16.row.col.f32.bf16.bf16.f32 "
        "{%0,%1,%2,%3}, {%4,%5,%6,%7}, {%8,%9}, {%0,%1,%2,%3};"
        : "+f"(c[0]), "+f"(c[1]), "+f"(c[2]), "+f"(c[3])
        : "r"(a[0]), "r"(a[1]), "r"(a[2]), "r"(a[3]), "r"(b[0]), "r"(b[1]));
}
#define STS16(addr, v) \
    asm volatile("st.shared.u16 [%0], %1;" :: "r"(addr), "h"((uint16_t)(v)) : "memory")

// silu via single-MUFU tanh: silu(x) = s + s*tanh(s), s = x/2
__device__ __forceinline__ float silu_f(float x) {
    float s = 0.5f * x, t;
    asm("tanh.approx.f32 %0, %1;" : "=f"(t) : "f"(s));
    return fmaf(s, t, s);
}

// ---------------- weight prep (unchanged, proven) ----------------
__global__ void prep_kernel(const float* __restrict__ W1, const float* __restrict__ W2) {
    int s = blockIdx.x, tid = threadIdx.x;
    for (int idx = tid; idx < 3584 + 4608; idx += blockDim.x) {
        float w; int off_hi, off_lo;
        if (idx < 3584) {                       // layer 1: n 0-63, k 0-55
            int n = idx / 56, k = idx % 56;
            w = (n < H_ && k < D_IN) ? W1[s * D_IN * H_ + k * H_ + n] : 0.0f;
            off_hi = W_B1H + idx; off_lo = W_B1L + idx;
        } else {                                // layer 2: n 0-63, k 0-71
            int j = idx - 3584;
            int n = j / 72, k = j % 72;
            w = (n < H_ && k < H_) ? W2[s * H_ * H_ + k * H_ + n] : 0.0f;
            off_hi = W_B2H + j; off_lo = W_B2L + j;
        }
        __nv_bfloat16 hi = __float2bfloat16(w);
        __nv_bfloat16 lo = __float2bfloat16(w - __bfloat162float(hi));
        g_W[s][off_hi] = __bfloat16_as_ushort(hi);
        g_W[s][off_lo] = __bfloat16_as_ushort(lo);
    }
}

// ---------------- main kernel ----------------
__global__ void __launch_bounds__(TPB, 2) atomic_mlp_mma(
    const float* __restrict__ desc,     // [N, A, D_IN]
    const int*   __restrict__ numbers,  // [A]
    const float* __restrict__ b1, const float* __restrict__ b2,
    const float* __restrict__ W3, const float* __restrict__ b3,
    float* __restrict__ out)            // [N, A]
{
    extern __shared__ __align__(128) unsigned char smem[];
    const uint32_t sb = smem_u32(smem);
    const int tid = threadIdx.x;
    const int wid = tid >> 5, lid = tid & 31;
    const int mbase = wid * 16;          // warp tile: m16 x n64
    const int g = lid >> 2, tig = lid & 3;
    const int a = blockIdx.x;
    const int s = numbers[a];

    float* sB1f = (float*)(smem + SB1);
    float* sB2f = (float*)(smem + SB2);
    float* sW3f = (float*)(smem + SW3);
    float* sB3f = (float*)(smem + SB3);

    // zero A1 panels (k-pad 39..47 must stay zero)
    for (int i = tid; i < 28672 / 16; i += TPB)
        ((float4*)smem)[i] = make_float4(0.f, 0.f, 0.f, 0.f);
    // copy species weight panels (contiguous 32 KB)
    {
        const float4* src = (const float4*)g_W[s];
        float4* dst = (float4*)(smem + B1H);
        for (int i = tid; i < 32768 / 16; i += TPB) dst[i] = src[i];
    }
    if (tid < 64) {
        sB1f[tid] = (tid < H_) ? b1[s * H_ + tid] : 0.0f;
        sB2f[tid] = (tid < H_) ? b2[s * H_ + tid] : 0.0f;
        sW3f[tid] = (tid < H_) ? W3[s * H_ + tid] : 0.0f;
    }
    if (tid == 0) *sB3f = b3[s];

    // ldmatrix lane offsets
    const int lm = lid >> 3, rin = lid & 7;
    const uint32_t aoff1 = (uint32_t)((mbase + rin + (lm & 1) * 8) * STR1 + (lm >> 1) * 16);
    const uint32_t boff1 = (uint32_t)((rin + (lm >> 1) * 8) * STR1 + (lm & 1) * 16);
    const uint32_t boff2 = (uint32_t)((rin + (lm >> 1) * 8) * STR2 + (lm & 1) * 16);

    const int chunk = blockIdx.y;
    for (int t = 0; t < 4; t++) {
        const int n0 = (chunk * 4 + t) * 128;

        // ---- stage desc tile -> A1 hi/lo panels ----
        {
            const float* dbase = desc + ((size_t)n0 * A_ + a) * D_IN;
            for (int idx = tid; idx < 128 * D_IN; idx += TPB) {
                int i = idx / D_IN, d = idx - i * D_IN;
                float x = dbase[(size_t)i * (A_ * D_IN) + d];
                uint32_t xb = __float_as_uint(x);
                uint32_t hb = xb & 0xFFFF0000u;                 // truncation split
                __nv_bfloat16 lo = __float2bfloat16(x - __uint_as_float(hb));
                uint32_t ad = sb + (uint32_t)(i * STR1 + d * 2);
                STS16(A1H + ad, (uint16_t)(xb >> 16));
                STS16(A1L + ad, __bfloat16_as_ushort(lo));
            }
        }
        __syncthreads();

        // ---- layer 1: acc[nj], nj=0..6 (n 0..55); n 56-63 all-pad, skipped ----
        float acc[7][4];
#pragma unroll
        for (int nj = 0; nj < 7; nj++)
#pragma unroll
            for (int r = 0; r < 4; r++) acc[nj][r] = 0.0f;

#pragma unroll
        for (int ks = 0; ks < 3; ks++) {
            const uint32_t kb = ks * 32;
            uint32_t ah[4], al[4], bh[16], bl[16];
            ldsm4(ah, sb + A1H + aoff1 + kb);
            ldsm4(al, sb + A1L + aoff1 + kb);
#pragma unroll
            for (int r = 0; r < 4; r++) {
                ldsm4(bh + 4 * r, sb + B1H + boff1 + r * 16 * STR1 + kb);
                ldsm4(bl + 4 * r, sb + B1L + boff1 + r * 16 * STR1 + kb);
            }
#pragma unroll
            for (int nj = 0; nj < 7; nj++) {
                mma16816(acc[nj], ah, bh + 2 * nj);
                mma16816(acc[nj], al, bh + 2 * nj);
                mma16816(acc[nj], ah, bl + 2 * nj);
            }
        }

        // ---- epilogue 1 (register-only): +b1, silu, split -> layer-2 A frags ----
        float h[7][4];
        {
#pragma unroll
            for (int nj = 0; nj < 7; nj++) {
                float2 bv = *(const float2*)&sB1f[8 * nj + 2 * tig];
                h[nj][0] = silu_f(acc[nj][0] + bv.x);
                h[nj][1] = silu_f(acc[nj][1] + bv.y);
                h[nj][2] = silu_f(acc[nj][2] + bv.x);
                h[nj][3] = silu_f(acc[nj][3] + bv.y);
            }
        }
        // repack: acc-frag(n-chunk) == A-frag(k-chunk). Ahi2[s] covers k [16s,16s+16).
        uint32_t Ahi2[4][4], Alo2[4][4];
#pragma unroll
        for (int sstep = 0; sstep < 4; sstep++) {
#pragma unroll
            for (int half = 0; half < 2; half++) {       // k-chunk 2s+half
                int c = 2 * sstep + half;
                float v0 = (c < 7) ? h[c][0] : 0.0f;
                float v1 = (c < 7) ? h[c][1] : 0.0f;
                float v2 = (c < 7) ? h[c][2] : 0.0f;
                float v3 = (c < 7) ? h[c][3] : 0.0f;
                uint32_t hb0 = __float_as_uint(v0) & 0xFFFF0000u;
                uint32_t hb1 = __float_as_uint(v1) & 0xFFFF0000u;
                uint32_t hb2 = __float_as_uint(v2) & 0xFFFF0000u;
                uint32_t hb3 = __float_as_uint(v3) & 0xFFFF0000u;
                Ahi2[sstep][2 * half]     = __byte_perm(hb0, hb1, 0x7632);
                Ahi2[sstep][2 * half + 1] = __byte_perm(hb2, hb3, 0x7632);
                uint32_t l01, l23;
                asm("cvt.rn.bf16x2.f32 %0, %1, %2;" : "=r"(l01)
                    : "f"(v1 - __uint_as_float(hb1)), "f"(v0 - __uint_as_float(hb0)));
                asm("cvt.rn.bf16x2.f32 %0, %1, %2;" : "=r"(l23)
                    : "f"(v3 - __uint_as_float(hb3)), "f"(v2 - __uint_as_float(hb2)));
                Alo2[sstep][2 * half]     = l01;
                Alo2[sstep][2 * half + 1] = l23;
            }
        }

        // ---- layer 2: A frags in registers, B from smem ----
        float acc2[7][4];
#pragma unroll
        for (int nj = 0; nj < 7; nj++)
#pragma unroll
            for (int r = 0; r < 4; r++) acc2[nj][r] = 0.0f;

#pragma unroll
        for (int ks = 0; ks < 4; ks++) {
            const uint32_t kb = ks * 32;
            uint32_t bh[16], bl[16];
#pragma unroll
            for (int r = 0; r < 4; r++) {
                ldsm4(bh + 4 * r, sb + B2H + boff2 + r * 16 * STR2 + kb);
                ldsm4(bl + 4 * r, sb + B2L + boff2 + r * 16 * STR2 + kb);
            }
#pragma unroll
            for (int nj = 0; nj < 7; nj++) {
                mma16816(acc2[nj], Ahi2[ks], bh + 2 * nj);
                mma16816(acc2[nj], Alo2[ks], bh + 2 * nj);
                mma16816(acc2[nj], Ahi2[ks], bl + 2 * nj);
            }
        }

        // ---- epilogue 2: +b2, silu, dot w3, quad-reduce, direct STG ----
        {
            float p0 = 0.f, p1 = 0.f;    // rows mbase+g, mbase+g+8
#pragma unroll
            for (int nj = 0; nj < 7; nj++) {
                float2 bv = *(const float2*)&sB2f[8 * nj + 2 * tig];
                float2 wv = *(const float2*)&sW3f[8 * nj + 2 * tig];
                const float* c = acc2[nj];
                p0 += silu_f(c[0] + bv.x) * wv.x + silu_f(c[1] + bv.y) * wv.y;
                p1 += silu_f(c[2] + bv.x) * wv.x + silu_f(c[3] + bv.y) * wv.y;
            }
            p0 += __shfl_xor_sync(0xFFFFFFFFu, p0, 1);
            p0 += __shfl_xor_sync(0xFFFFFFFFu, p0, 2);
            p1 += __shfl_xor_sync(0xFFFFFFFFu, p1, 1);
            p1 += __shfl_xor_sync(0xFFFFFFFFu, p1, 2);
            if (tig == 0) {
                float b3s = *sB3f;
                out[(size_t)(n0 + mbase + g) * A_ + a]     = p0 + b3s;
                out[(size_t)(n0 + mbase + 8 + g) * A_ + a] = p1 + b3s;
            }
        }
        __syncthreads();   // protect A1 panels before next tile's staging
    }
}

extern "C" void kernel_launch(void* const* d_in, const int* in_sizes, int n_in,
                              void* d_out, int out_size) {
    const float* desc    = (const float*)d_in[0];
    const int*   numbers = (const int*)  d_in[1];
    const float* W1      = (const float*)d_in[2];
    const float* b1      = (const float*)d_in[3];
    const float* W2      = (const float*)d_in[4];
    const float* b2      = (const float*)d_in[5];
    const float* W3      = (const float*)d_in[6];
    const float* b3      = (const float*)d_in[7];
    float* out = (float*)d_out;

    const int N = in_sizes[0] / (A_ * D_IN);   // 4096
    prep_kernel<<<S_, 256>>>(W1, W2);
    cudaFuncSetAttribute(atomic_mlp_mma, cudaFuncAttributeMaxDynamicSharedMemorySize, SMEM_BYTES);
    dim3 grid(A_, (unsigned)(N / 512));        // (256, 8)
    atomic_mlp_mma<<<grid, TPB, SMEM_BYTES>>>(desc, numbers, b1, b2, W3, b3, out);
}